// round 4
// baseline (speedup 1.0000x reference)
#include <cuda_runtime.h>
#include <cstdint>
#include <cstddef>

// Problem constants
#define IN_DIM  512
#define OUT_DIM 256
#define NMID    1280
#define NNODES  1792
#define BATCH   16384

#define TBLK 128          // node-panel width
#define NB   (NMID/TBLK)  // 10 panels
#define MT   128          // rows per CTA in panel kernel
#define KC   16           // k-chunk

// Scratch (device globals: allocation-free per harness rules)
__device__ float g_res[(size_t)BATCH * NNODES];    // results buffer [B][1792]
__device__ float g_effW[(size_t)NNODES * NMID];    // weight * connectivity

// ---------------------------------------------------------------------------
// prep: effW = weight * connectivity
// ---------------------------------------------------------------------------
__global__ void prep_kernel(const float* __restrict__ w, const int* __restrict__ conn) {
    int i = blockIdx.x * blockDim.x + threadIdx.x;
    const int tot = NNODES * NMID;
    for (; i < tot; i += gridDim.x * blockDim.x)
        g_effW[i] = w[i] * (float)conn[i];
}

// ---------------------------------------------------------------------------
// init: res[:, :512] = x
// ---------------------------------------------------------------------------
__global__ void init_kernel(const float* __restrict__ x) {
    size_t i = (size_t)blockIdx.x * blockDim.x + threadIdx.x;
    const size_t tot = (size_t)BATCH * IN_DIM;
    const size_t stride = (size_t)gridDim.x * blockDim.x;
    for (; i < tot; i += stride) {
        size_t b = i >> 9;        // /512
        size_t k = i & 511;
        g_res[b * NNODES + k] = x[i];
    }
}

// ---------------------------------------------------------------------------
// Panel kernel: fused GEMM (P = res[:, :K] @ effW[:, panel]) + triangular sweep
//   CTA: 128 rows x 128 cols, 256 threads, thread tile 8x8, f32x2 packed FMA.
// Smem layout (floats):
//   As[16][132] transposed A chunk   (2112)
//   Bs[16][128] W chunk              (2048)
//   P [128][133] panel accum/values  (17024)  pad 133 -> conflict-free col reads
//   Wd[128][128] diagonal W block    (16384)
//   sb[128], se[128]                 (256)
// total = 37824 floats = 151296 bytes
// ---------------------------------------------------------------------------
#define SMEM_FLOATS (16*132 + 16*128 + 128*133 + 128*128 + 256)
#define SMEM_BYTES  (SMEM_FLOATS * 4)

__global__ void __launch_bounds__(256, 1)
panel_kernel(const float* __restrict__ bias, const int* __restrict__ exist, int t) {
    extern __shared__ float smem[];
    float* As = smem;                 // [KC][132]
    float* Bs = As + KC * 132;        // [KC][128]
    float* P  = Bs + KC * 128;        // [128][133]
    float* Wd = P + 128 * 133;        // [128][128]
    float* sb = Wd + 128 * 128;       // [128]
    float* se = sb + 128;             // [128]

    const int c0 = t * TBLK;          // mid-column offset of this panel
    const int K  = IN_DIM + c0;       // prefix dot length (multiple of 16)
    const int rowbase = blockIdx.x * MT;
    const int tid = threadIdx.x;
    const int tx = tid & 15;          // col group 0..15
    const int ty = tid >> 4;          // row group 0..15

    // 8 rows x 8 cols accumulators, packed as 8 x 4 f32x2
    unsigned long long acc[8][4];
#pragma unroll
    for (int i = 0; i < 8; i++)
#pragma unroll
        for (int j = 0; j < 4; j++) acc[i][j] = 0ULL;

    for (int k0 = 0; k0 < K; k0 += KC) {
        // --- load A chunk [128 rows x 16 k] transposed into As[kk][r] ---
#pragma unroll
        for (int l = 0; l < 2; l++) {
            int idx = tid + l * 256;          // 0..511 float4s
            int r   = idx >> 2;               // 0..127
            int kq  = idx & 3;                // 0..3
            float4 v = *(const float4*)&g_res[(size_t)(rowbase + r) * NNODES + k0 + kq * 4];
            As[(kq * 4 + 0) * 132 + r] = v.x;
            As[(kq * 4 + 1) * 132 + r] = v.y;
            As[(kq * 4 + 2) * 132 + r] = v.z;
            As[(kq * 4 + 3) * 132 + r] = v.w;
        }
        // --- load W chunk [16 k x 128 cols] ---
#pragma unroll
        for (int l = 0; l < 2; l++) {
            int idx = tid + l * 256;          // 0..511 float4s
            int kk  = idx >> 5;               // 0..15
            int cq  = idx & 31;               // 0..31
            *(float4*)&Bs[kk * 128 + cq * 4] =
                *(const float4*)&g_effW[(size_t)(k0 + kk) * NMID + c0 + cq * 4];
        }
        __syncthreads();

#pragma unroll
        for (int kk = 0; kk < KC; kk++) {
            unsigned long long bb[4];
            const unsigned long long* bp =
                (const unsigned long long*)&Bs[kk * 128 + tx * 8];
            bb[0] = bp[0]; bb[1] = bp[1]; bb[2] = bp[2]; bb[3] = bp[3];
#pragma unroll
            for (int i = 0; i < 8; i++) {
                float av = As[kk * 132 + ty * 8 + i];
                unsigned int au = __float_as_uint(av);
                unsigned long long ap;
                asm("mov.b64 %0, {%1, %1};" : "=l"(ap) : "r"(au));
#pragma unroll
                for (int j = 0; j < 4; j++)
                    asm("fma.rn.f32x2 %0, %1, %2, %0;"
                        : "+l"(acc[i][j]) : "l"(ap), "l"(bb[j]));
            }
        }
        __syncthreads();
    }

    // --- dump accumulators to P ---
#pragma unroll
    for (int i = 0; i < 8; i++) {
        int r = ty * 8 + i;
#pragma unroll
        for (int j = 0; j < 4; j++) {
            unsigned int lo, hi;
            asm("mov.b64 {%0, %1}, %2;" : "=r"(lo), "=r"(hi) : "l"(acc[i][j]));
            P[r * 133 + tx * 8 + 2 * j]     = __uint_as_float(lo);
            P[r * 133 + tx * 8 + 2 * j + 1] = __uint_as_float(hi);
        }
    }
    // --- load diagonal block Wd[j][i] = effW[512+c0+j][c0+i], bias, exist ---
#pragma unroll
    for (int l = 0; l < 16; l++) {
        int idx = tid + l * 256;              // 0..4095 float4s
        int j  = idx >> 5;
        int cq = idx & 31;
        *(float4*)&Wd[j * 128 + cq * 4] =
            *(const float4*)&g_effW[(size_t)(IN_DIM + c0 + j) * NMID + c0 + cq * 4];
    }
    if (tid < 128) {
        sb[tid] = bias[c0 + tid];
        se[tid] = (float)exist[c0 + tid];
    }
    __syncthreads();

    // --- triangular sweep: one thread per row, 4-way split accumulator ---
    if (tid < 128) {
        float* Pr = &P[(size_t)tid * 133];
        for (int i = 0; i < TBLK; i++) {
            float a0 = Pr[i], a1 = 0.f, a2 = 0.f, a3 = 0.f;
            int j = 0;
            for (; j + 4 <= i; j += 4) {
                a0 += Pr[j]     * Wd[(j)     * 128 + i];
                a1 += Pr[j + 1] * Wd[(j + 1) * 128 + i];
                a2 += Pr[j + 2] * Wd[(j + 2) * 128 + i];
                a3 += Pr[j + 3] * Wd[(j + 3) * 128 + i];
            }
            for (; j < i; j++) a0 += Pr[j] * Wd[j * 128 + i];
            float z = (a0 + a1) + (a2 + a3);
            float v = 1.0f / (1.0f + __expf(-z));   // sigmoid
            v = (v + sb[i]) * se[i];                 // bias AFTER sigmoid, then existence
            Pr[i] = v;
        }
    }
    __syncthreads();

    // --- coalesced write-back of the 128 new columns ---
#pragma unroll
    for (int l = 0; l < 64; l++) {
        int idx = tid + l * 256;                 // 0..16383
        int r = idx >> 7, c = idx & 127;
        g_res[(size_t)(rowbase + r) * NNODES + IN_DIM + c0 + c] = P[r * 133 + c];
    }
}

// ---------------------------------------------------------------------------
// gather output: out = res[:, -256:]
// ---------------------------------------------------------------------------
__global__ void out_kernel(float* __restrict__ out) {
    size_t i = (size_t)blockIdx.x * blockDim.x + threadIdx.x;
    const size_t tot = (size_t)BATCH * OUT_DIM;
    const size_t stride = (size_t)gridDim.x * blockDim.x;
    for (; i < tot; i += stride) {
        size_t b = i >> 8;        // /256
        size_t o = i & 255;
        out[i] = g_res[b * NNODES + (NNODES - OUT_DIM) + o];
    }
}

// ---------------------------------------------------------------------------
// Blocked lower-triangular solve of the NEAT recurrence:
//   10 panels of 128 nodes; per panel: dense GEMM over the known prefix
//   (fp32x2 packed FMA) fused with an in-smem sequential triangular sweep.
extern "C" void kernel_launch(void* const* d_in, const int* in_sizes, int n_in,
                              void* d_out, int out_size) {
    const float* x     = (const float*)d_in[0];   // [16384, 512]
    const float* w     = (const float*)d_in[1];   // [1792, 1280]
    const float* bias  = (const float*)d_in[2];   // [1280]
    const int*   conn  = (const int*)d_in[3];     // [1792, 1280]
    const int*   exist = (const int*)d_in[4];     // [1280]
    float* out = (float*)d_out;                   // [16384, 256]

    cudaFuncSetAttribute(panel_kernel,
                         cudaFuncAttributeMaxDynamicSharedMemorySize, SMEM_BYTES);

    prep_kernel<<<1024, 256>>>(w, conn);
    init_kernel<<<2048, 256>>>(x);
    for (int t = 0; t < NB; t++)
        panel_kernel<<<BATCH / MT, 256, SMEM_BYTES>>>(bias, exist, t);
    out_kernel<<<2048, 256>>>(out);
}